// round 16
// baseline (speedup 1.0000x reference)
#include <cuda_runtime.h>
#include <cuda_bf16.h>

#define Bq 256
#define Tq 512
#define Kq 128
#define SOS 0
#define EOSI 1
#define NCTA 148   // <= GB300 SM count: every CTA lands on its own SM (wave 1)
#define NSOLO 40   // 40 solo + 108 sequential pairs = 256 batches

__device__ float g_E[Kq * Kq];    // exp(trans), row-major
__device__ float g_ET[Kq * Kq];   // transpose of g_E
__device__ int   g_perm[Bq];      // batch index sorted by descending length
__device__ int   g_len[Bq];       // sequence length per batch

// ---------------- prep: E, E^T, lengths, rank permutation ----------------
__global__ void prep_kernel(const float* __restrict__ trans,
                            const float* __restrict__ mask) {
    if (blockIdx.x < 64) {
        int i = blockIdx.x * 256 + threadIdx.x;
        float v = expf(trans[i]);          // exp(-10000) -> exactly 0
        g_E[i] = v;
        int r = i >> 7, cc = i & 127;
        g_ET[cc * Kq + r] = v;
    } else {
        __shared__ int slen[Bq];
        int tid = threadIdx.x, w = tid >> 5, lane = tid & 31;
        for (int r = w; r < Bq; r += 8) {
            float s = 0.f;
            const float* mr = mask + (size_t)r * Tq;
            for (int i = lane; i < Tq; i += 32) s += mr[i];
            #pragma unroll
            for (int o = 16; o > 0; o >>= 1) s += __shfl_xor_sync(0xffffffffu, s, o);
            if (lane == 0) slen[r] = (int)(s + 0.5f);
        }
        __syncthreads();
        int L = slen[tid];
        g_len[tid] = L;
        int rank = 0;
        for (int j = 0; j < Bq; j++) {
            int Lj = slen[j];
            rank += (Lj > L) || (Lj == L && j < tid);
        }
        g_perm[rank] = tid;
    }
}

// bf16-vector dot: 16 LDS.128 deliver 128 bf16; even idx exact via SHF<<16,
// odd idx uses the raw word (neighbor bits = <2^-8 mantissa noise, common-mode
// cancels through pivot normalization). fp32 accumulate, 8 chains.
#define DOTB(VRES, PIVOT, PU)                                                    \
    {                                                                            \
        uint4 r0 = (PU)[0];                                                      \
        PIVOT = __uint_as_float(r0.y << 16);             /* p[2], exact */       \
        float a0, a1, a2, a3, a4, a5, a6, a7;                                    \
        a0 = e[0] * __uint_as_float(r0.x << 16);                                 \
        a1 = e[1] * __uint_as_float(r0.x);                                       \
        a2 = e[2] * __uint_as_float(r0.y << 16);                                 \
        a3 = e[3] * __uint_as_float(r0.y);                                       \
        a4 = e[4] * __uint_as_float(r0.z << 16);                                 \
        a5 = e[5] * __uint_as_float(r0.z);                                       \
        a6 = e[6] * __uint_as_float(r0.w << 16);                                 \
        a7 = e[7] * __uint_as_float(r0.w);                                       \
        _Pragma("unroll")                                                        \
        for (int ii = 1; ii < 16; ii++) {                                        \
            uint4 r = (PU)[ii];                                                  \
            a0 = fmaf(e[8 * ii],     __uint_as_float(r.x << 16), a0);            \
            a1 = fmaf(e[8 * ii + 1], __uint_as_float(r.x),       a1);            \
            a2 = fmaf(e[8 * ii + 2], __uint_as_float(r.y << 16), a2);            \
            a3 = fmaf(e[8 * ii + 3], __uint_as_float(r.y),       a3);            \
            a4 = fmaf(e[8 * ii + 4], __uint_as_float(r.z << 16), a4);            \
            a5 = fmaf(e[8 * ii + 5], __uint_as_float(r.z),       a5);            \
            a6 = fmaf(e[8 * ii + 6], __uint_as_float(r.w << 16), a6);            \
            a7 = fmaf(e[8 * ii + 7], __uint_as_float(r.w),       a7);            \
        }                                                                        \
        VRES = ((a0 + a1) + (a2 + a3)) + ((a4 + a5) + (a6 + a7));                \
    }

// ---------------- main CRF scan: fwd+bwd half-chains, bf16 state, 1 CTA/SM ----------
__global__ void __launch_bounds__(256, 1) crf_main_kernel(
    const float* __restrict__ h, float* __restrict__ out)
{
    int c = blockIdx.x;
    int tid = threadIdx.x;
    bool isF = tid < 128;            // warps 0-3 forward, 4-7 backward
    int k = tid & 127;
    int lane = tid & 31, w4 = (tid >> 5) & 3;

    int nb, r0, r1;
    if (c < NSOLO) { nb = 1; r0 = c;  r1 = 0; }
    else           { nb = 2; r0 = c;  r1 = 295 - c; }   // pairs (c, 295-c)

    __shared__ __align__(16) __nv_bfloat16 pbuf[2][Kq];   // forward state (bf16)
    __shared__ __align__(16) __nv_bfloat16 qbuf[2][Kq];   // backward state (bf16)
    __shared__ __align__(16) float qres[Kq];
    __shared__ float fred[4];
    __shared__ float sCb;

    // this thread's matrix row, scalar fp32: E row k (fwd) or E^T row k (bwd)
    float e[Kq];
    {
        const float4* er = reinterpret_cast<const float4*>(
            (isF ? g_E : g_ET) + k * Kq);
        #pragma unroll
        for (int i = 0; i < Kq / 4; i++) {
            float4 f = er[i];
            e[4 * i] = f.x; e[4 * i + 1] = f.y;
            e[4 * i + 2] = f.z; e[4 * i + 3] = f.w;
        }
    }
    float uk = g_E[EOSI * Kq + k];   // u[k] = E[EOS,k] (backward init)

    for (int bi = 0; bi < nb; bi++) {
        int b = g_perm[bi == 0 ? r0 : r1] & (Bq - 1);
        int L = g_len[b];
        int m = (L + 1) >> 1;        // forward steps (>=1); backward = L-m

        const float* hb = h + (size_t)b * Tq * Kq + k;
        float Cacc = 0.0f;

        if (isF) {
            // ---------------- forward: p_m = M_{m-1}...M_0 p_0 ----------------
            float ha0 = hb[0];
            float ha1 = hb[(size_t)1 * Kq];
            float ha2 = hb[(size_t)2 * Kq];

            float ehc = __expf(ha0);
            pbuf[1][k] = __float2bfloat16_rn(e[0] * ehc);   // E[k,SOS]*e^{h0}
            asm volatile("bar.sync 1, 128;" ::: "memory");

            ehc = __expf(ha1);
            float hy = ha2, hx = 0.f;
            int t = 1;

#define STEP_F(LOADR, EXPR)                                                      \
            {                                                                    \
                int tp = t + 2;                                                  \
                LOADR = (tp < Tq) ? hb[(size_t)tp * Kq] : 0.f;                   \
                float ehn = __expf(EXPR);                                        \
                const uint4* pu =                                                \
                    reinterpret_cast<const uint4*>(pbuf[t & 1]);                 \
                float v, pivot;                                                  \
                DOTB(v, pivot, pu);                                              \
                float ef = __fdividef(ehc, pivot);                               \
                Cacc += __logf(pivot);                                           \
                pbuf[(t + 1) & 1][k] = __float2bfloat16_rn(v * ef);              \
                asm volatile("bar.sync 1, 128;" ::: "memory");                   \
                ehc = ehn;                                                       \
                t++;                                                             \
            }
            while (t + 2 <= m) { STEP_F(hx, hy); STEP_F(hy, hx); }
            if (t < m) STEP_F(hx, hy);
#undef STEP_F
        } else {
            // ---------------- backward: q^T = u^T M_{L-1}...M_m ----------------
            int cnt = L - m;                 // = L>>1
            float v = uk;
            float pivot = 1.0f;
            if (cnt > 0) {
                int s = L - 1;
                float ehc = __expf(hb[(size_t)s * Kq]);
                float hy = (s - 1 >= 0) ? hb[(size_t)(s - 1) * Kq] : 0.f;
                float hx = 0.f;
                int i = 0;

#define STEP_B(LOADR, EXPR)                                                      \
                {                                                                \
                    int sp = s - 2;                                              \
                    LOADR = (sp >= 0) ? hb[(size_t)sp * Kq] : 0.f;               \
                    float ehn = __expf(EXPR);                                    \
                    float ef = __fdividef(ehc, pivot);                           \
                    Cacc += __logf(pivot);                                       \
                    qbuf[i & 1][k] = __float2bfloat16_rn(v * ef);                \
                    asm volatile("bar.sync 2, 128;" ::: "memory");               \
                    const uint4* pu =                                            \
                        reinterpret_cast<const uint4*>(qbuf[i & 1]);             \
                    DOTB(v, pivot, pu);                                          \
                    ehc = ehn;                                                   \
                    i++; s--;                                                    \
                }
                while (i + 2 <= cnt) { STEP_B(hx, hy); STEP_B(hy, hx); }
                if (i < cnt) STEP_B(hx, hy);
#undef STEP_B
            }
            qres[k] = v;                 // final backward vector kept in fp32
            if (k == 0) sCb = Cacc;
        }

        __syncthreads();   // both chains done; qres, sCb, pbuf[m&1] visible

        // out[b] = C_f + C_b + log( sum_k p_m[k] * q_m[k] )
        if (isF) {
            float val = __bfloat162float(pbuf[m & 1][k]) * qres[k];
            #pragma unroll
            for (int o = 16; o > 0; o >>= 1)
                val += __shfl_xor_sync(0xffffffffu, val, o);
            if (lane == 0) fred[w4] = val;
            asm volatile("bar.sync 1, 128;" ::: "memory");
            if (tid == 0)
                out[b] = Cacc + sCb +
                         __logf(fred[0] + fred[1] + fred[2] + fred[3]);
        }
        __syncthreads();   // protect shared reuse for next batch
    }
}

extern "C" void kernel_launch(void* const* d_in, const int* in_sizes, int n_in,
                              void* d_out, int out_size) {
    const float* h     = (const float*)d_in[0];
    const float* trans = (const float*)d_in[1];
    const float* mask  = (const float*)d_in[2];
    float* out = (float*)d_out;
    (void)in_sizes; (void)n_in; (void)out_size;

    prep_kernel<<<65, 256>>>(trans, mask);
    crf_main_kernel<<<NCTA, 256>>>(h, out);
}

// round 17
// speedup vs baseline: 1.1556x; 1.1556x over previous
#include <cuda_runtime.h>
#include <cuda_bf16.h>

#define Bq 256
#define Tq 512
#define Kq 128
#define SOS 0
#define EOSI 1
#define NCTA 148   // <= GB300 SM count: every CTA lands on its own SM (wave 1)
#define NSOLO 40   // 40 solo + 108 sequential pairs = 256 batches

__device__ float g_E[Kq * Kq];                 // exp(trans), fp32 (epilogue/init)
__device__ __nv_bfloat16 g_Ebf[Kq * Kq];       // exp(trans), bf16 row-major
__device__ __nv_bfloat16 g_ETbf[Kq * Kq];      // transpose, bf16
__device__ int g_perm[Bq];                     // batch idx sorted by desc length
__device__ int g_len[Bq];                      // sequence length per batch

// ---------------- prep: E (fp32+bf16), E^T (bf16), lengths, permutation ----------
__global__ void prep_kernel(const float* __restrict__ trans,
                            const float* __restrict__ mask) {
    if (blockIdx.x < 64) {
        int i = blockIdx.x * 256 + threadIdx.x;
        float v = expf(trans[i]);          // exp(-10000) -> exactly 0
        g_E[i] = v;
        __nv_bfloat16 bv = __float2bfloat16_rn(v);
        g_Ebf[i] = bv;
        int r = i >> 7, cc = i & 127;
        g_ETbf[cc * Kq + r] = bv;
    } else {
        __shared__ int slen[Bq];
        int tid = threadIdx.x, w = tid >> 5, lane = tid & 31;
        for (int r = w; r < Bq; r += 8) {
            float s = 0.f;
            const float* mr = mask + (size_t)r * Tq;
            for (int i = lane; i < Tq; i += 32) s += mr[i];
            #pragma unroll
            for (int o = 16; o > 0; o >>= 1) s += __shfl_xor_sync(0xffffffffu, s, o);
            if (lane == 0) slen[r] = (int)(s + 0.5f);
        }
        __syncthreads();
        int L = slen[tid];
        g_len[tid] = L;
        int rank = 0;
        for (int j = 0; j < Bq; j++) {
            int Lj = slen[j];
            rank += (Lj > L) || (Lj == L && j < tid);
        }
        g_perm[rank] = tid;
    }
}

__device__ __forceinline__ __nv_bfloat162 bf2(unsigned u) {
    union { unsigned u; __nv_bfloat162 b; } cv; cv.u = u; return cv.b;
}

// bf16x2 dot: 16 LDS.128 + 64 HFMA2, 16 packed accumulators (scalar depth<=8).
// PIVOT = p[2] (bf16->fp32 exact, consistent for all threads).
#define DOTH(VRES, PIVOT, PU)                                                    \
    {                                                                            \
        __nv_bfloat162 acc[16];                                                  \
        uint4 r = (PU)[0];                                                       \
        PIVOT = __low2float(bf2(r.y));                   /* p[2] */              \
        acc[0] = __hmul2(e2[0], bf2(r.x));                                       \
        acc[1] = __hmul2(e2[1], bf2(r.y));                                       \
        acc[2] = __hmul2(e2[2], bf2(r.z));                                       \
        acc[3] = __hmul2(e2[3], bf2(r.w));                                       \
        r = (PU)[1];                                                             \
        acc[4] = __hmul2(e2[4], bf2(r.x));                                       \
        acc[5] = __hmul2(e2[5], bf2(r.y));                                       \
        acc[6] = __hmul2(e2[6], bf2(r.z));                                       \
        acc[7] = __hmul2(e2[7], bf2(r.w));                                       \
        r = (PU)[2];                                                             \
        acc[8]  = __hmul2(e2[8],  bf2(r.x));                                     \
        acc[9]  = __hmul2(e2[9],  bf2(r.y));                                     \
        acc[10] = __hmul2(e2[10], bf2(r.z));                                     \
        acc[11] = __hmul2(e2[11], bf2(r.w));                                     \
        r = (PU)[3];                                                             \
        acc[12] = __hmul2(e2[12], bf2(r.x));                                     \
        acc[13] = __hmul2(e2[13], bf2(r.y));                                     \
        acc[14] = __hmul2(e2[14], bf2(r.z));                                     \
        acc[15] = __hmul2(e2[15], bf2(r.w));                                     \
        _Pragma("unroll")                                                        \
        for (int ii = 4; ii < 16; ii++) {                                        \
            uint4 q = (PU)[ii];                                                  \
            acc[(4 * ii)     & 15] = __hfma2(e2[4 * ii],     bf2(q.x),           \
                                             acc[(4 * ii)     & 15]);            \
            acc[(4 * ii + 1) & 15] = __hfma2(e2[4 * ii + 1], bf2(q.y),           \
                                             acc[(4 * ii + 1) & 15]);            \
            acc[(4 * ii + 2) & 15] = __hfma2(e2[4 * ii + 2], bf2(q.z),           \
                                             acc[(4 * ii + 2) & 15]);            \
            acc[(4 * ii + 3) & 15] = __hfma2(e2[4 * ii + 3], bf2(q.w),           \
                                             acc[(4 * ii + 3) & 15]);            \
        }                                                                        \
        _Pragma("unroll")                                                        \
        for (int o = 8; o > 0; o >>= 1)                                          \
            for (int ii = 0; ii < o; ii++)                                       \
                acc[ii] = __hadd2(acc[ii], acc[ii + o]);                         \
        VRES = __low2float(acc[0]) + __high2float(acc[0]);                       \
    }

// ---------------- main CRF scan: fwd+bwd half-chains, bf16 HFMA2, 1 CTA/SM ---------
__global__ void __launch_bounds__(256, 1) crf_main_kernel(
    const float* __restrict__ h, float* __restrict__ out)
{
    int c = blockIdx.x;
    int tid = threadIdx.x;
    bool isF = tid < 128;            // warps 0-3 forward, 4-7 backward
    int k = tid & 127;
    int lane = tid & 31, w4 = (tid >> 5) & 3;

    int nb, r0, r1;
    if (c < NSOLO) { nb = 1; r0 = c;  r1 = 0; }
    else           { nb = 2; r0 = c;  r1 = 295 - c; }   // pairs (c, 295-c)

    __shared__ __align__(16) __nv_bfloat16 pbuf[2][Kq];   // forward state
    __shared__ __align__(16) __nv_bfloat16 qbuf[2][Kq];   // backward state
    __shared__ __align__(16) float qres[Kq];
    __shared__ float fred[4];
    __shared__ float sCb;

    // this thread's matrix row as 64 packed bf16x2 registers
    __nv_bfloat162 e2[Kq / 2];
    {
        const uint4* er = reinterpret_cast<const uint4*>(
            (isF ? g_Ebf : g_ETbf) + k * Kq);
        #pragma unroll
        for (int i = 0; i < 16; i++) {
            uint4 r = er[i];
            e2[4 * i]     = bf2(r.x);
            e2[4 * i + 1] = bf2(r.y);
            e2[4 * i + 2] = bf2(r.z);
            e2[4 * i + 3] = bf2(r.w);
        }
    }
    float uk = g_E[EOSI * Kq + k];   // u[k] = E[EOS,k] (backward init, fp32)

    for (int bi = 0; bi < nb; bi++) {
        int b = g_perm[bi == 0 ? r0 : r1] & (Bq - 1);
        int L = g_len[b];
        int m = (L + 1) >> 1;        // forward steps (>=1); backward = L-m

        const float* hb = h + (size_t)b * Tq * Kq + k;
        float Cacc = 0.0f;

        if (isF) {
            // ---------------- forward: p_m = M_{m-1}...M_0 p_0 ----------------
            float ha0 = hb[0];
            float ha1 = hb[(size_t)1 * Kq];
            float ha2 = hb[(size_t)2 * Kq];

            float ehc = __expf(ha0);
            // peel t=0: P_1[k] = E[k,SOS]*e^{h0}, pivot = 1
            pbuf[1][k] = __float2bfloat16_rn(__low2float(e2[0]) * ehc);
            asm volatile("bar.sync 1, 128;" ::: "memory");

            ehc = __expf(ha1);
            float hy = ha2, hx = 0.f;
            int t = 1;

#define STEP_F(LOADR, EXPR)                                                      \
            {                                                                    \
                int tp = t + 2;                                                  \
                LOADR = (tp < Tq) ? hb[(size_t)tp * Kq] : 0.f;                   \
                float ehn = __expf(EXPR);                                        \
                const uint4* pu =                                                \
                    reinterpret_cast<const uint4*>(pbuf[t & 1]);                 \
                float v, pivot;                                                  \
                DOTH(v, pivot, pu);                                              \
                float ef = __fdividef(ehc, pivot);                               \
                Cacc += __logf(pivot);                                           \
                pbuf[(t + 1) & 1][k] = __float2bfloat16_rn(v * ef);              \
                asm volatile("bar.sync 1, 128;" ::: "memory");                   \
                ehc = ehn;                                                       \
                t++;                                                             \
            }
            while (t + 2 <= m) { STEP_F(hx, hy); STEP_F(hy, hx); }
            if (t < m) STEP_F(hx, hy);
#undef STEP_F
        } else {
            // ---------------- backward: q^T = u^T M_{L-1}...M_m ----------------
            int cnt = L - m;                 // = L>>1
            float v = uk;
            float pivot = 1.0f;
            if (cnt > 0) {
                int s = L - 1;
                float ehc = __expf(hb[(size_t)s * Kq]);
                float hy = (s - 1 >= 0) ? hb[(size_t)(s - 1) * Kq] : 0.f;
                float hx = 0.f;
                int i = 0;

#define STEP_B(LOADR, EXPR)                                                      \
                {                                                                \
                    int sp = s - 2;                                              \
                    LOADR = (sp >= 0) ? hb[(size_t)sp * Kq] : 0.f;               \
                    float ehn = __expf(EXPR);                                    \
                    float ef = __fdividef(ehc, pivot);                           \
                    Cacc += __logf(pivot);                                       \
                    qbuf[i & 1][k] = __float2bfloat16_rn(v * ef);                \
                    asm volatile("bar.sync 2, 128;" ::: "memory");               \
                    const uint4* pu =                                            \
                        reinterpret_cast<const uint4*>(qbuf[i & 1]);             \
                    DOTH(v, pivot, pu);                                          \
                    ehc = ehn;                                                   \
                    i++; s--;                                                    \
                }
                while (i + 2 <= cnt) { STEP_B(hx, hy); STEP_B(hy, hx); }
                if (i < cnt) STEP_B(hx, hy);
#undef STEP_B
            }
            qres[k] = v;                 // final backward vector in fp32
            if (k == 0) sCb = Cacc;
        }

        __syncthreads();   // both chains done; qres, sCb, pbuf[m&1] visible

        // out[b] = C_f + C_b + log( sum_k p_m[k] * q_m[k] )
        if (isF) {
            float val = __bfloat162float(pbuf[m & 1][k]) * qres[k];
            #pragma unroll
            for (int o = 16; o > 0; o >>= 1)
                val += __shfl_xor_sync(0xffffffffu, val, o);
            if (lane == 0) fred[w4] = val;
            asm volatile("bar.sync 1, 128;" ::: "memory");
            if (tid == 0)
                out[b] = Cacc + sCb +
                         __logf(fred[0] + fred[1] + fred[2] + fred[3]);
        }
        __syncthreads();   // protect shared reuse for next batch
    }
}

extern "C" void kernel_launch(void* const* d_in, const int* in_sizes, int n_in,
                              void* d_out, int out_size) {
    const float* h     = (const float*)d_in[0];
    const float* trans = (const float*)d_in[1];
    const float* mask  = (const float*)d_in[2];
    float* out = (float*)d_out;
    (void)in_sizes; (void)n_in; (void)out_size;

    prep_kernel<<<65, 256>>>(trans, mask);
    crf_main_kernel<<<NCTA, 256>>>(h, out);
}